// round 2
// baseline (speedup 1.0000x reference)
#include <cuda_runtime.h>
#include <cuda_bf16.h>
#include <cstdint>

// Problem constants
#define Bn   128
#define Sn   512
#define Ln   64
#define NPAIRS ((Bn-1)*Sn)      // 65024
#define PPB  128                 // pairs per block in alpha kernel
#define NBLK (NPAIRS/PPB)        // 508
#define NQ   (Bn*Sn)             // 65536 emit rows

#define LOG2E 1.4426950408889634f
#define LN2f  0.6931471805599453f

// Scratch (static device globals -- no allocation allowed)
__device__ double g_alpha[Ln];
__device__ double g_score;
__device__ float  gExpT[Ln*Ln];          // gExpT[j*64+i] = 2^(T[i][j]*log2e)
__device__ float  gExpE[(size_t)Ln*NQ];  // gExpE[j*65536+q] = 2^(emit[q][j]*log2e)

__device__ __forceinline__ float ex2f(float x){ float y; asm("ex2.approx.f32 %0, %1;" : "=f"(y) : "f"(x)); return y; }
__device__ __forceinline__ float lg2f_(float x){ float y; asm("lg2.approx.f32 %0, %1;" : "=f"(y) : "f"(x)); return y; }

// ---------------------------------------------------------------------------
// Kernel 0: zero accumulators + build transposed exp(T)
// ---------------------------------------------------------------------------
__global__ void init_kernel(const float* __restrict__ trans){
    int t = threadIdx.x;
    if (t < Ln)  g_alpha[t] = 0.0;
    if (t == 64) g_score = 0.0;
    #pragma unroll
    for (int it = 0; it < 16; ++it){
        int o = t + it*256;          // o = j*64 + i
        int i = o & 63, j = o >> 6;
        gExpT[o] = ex2f(trans[i*64 + j] * LOG2E);
    }
}

// ---------------------------------------------------------------------------
// Kernel 0b: tiled transpose of emit with exp2 applied.
// gExpE[j][q] = 2^(emit[q][j]*log2e).  Block: 32 q-rows x 64 j.
// ---------------------------------------------------------------------------
__global__ __launch_bounds__(256) void transpose_exp_kernel(const float* __restrict__ emit){
    __shared__ float tile[32][65];
    int q0 = blockIdx.x * 32;
    int t  = threadIdx.x;
    int c  = t & 63, r0 = t >> 6;      // 4 rows per iter
    #pragma unroll
    for (int it = 0; it < 8; ++it){
        int r = r0 + it*4;
        tile[r][c] = emit[(size_t)(q0 + r)*Ln + c];
    }
    __syncthreads();
    int qq = t & 31, j0 = t >> 5;      // 8 j's per iter
    #pragma unroll
    for (int it = 0; it < 8; ++it){
        int j = j0 + it*8;
        gExpE[(size_t)j*NQ + q0 + qq] = ex2f(tile[qq][j] * LOG2E);
    }
}

// ---------------------------------------------------------------------------
// Kernel 1: alpha partial sums.
// Each block handles 128 pairs.  Thread tile: 4 i x 8 pairs (32 accumulators).
// acc[i][p] = sum_j expT[i][j] * expE[p][j]; c = log2(acc)*ln2; reduce over pairs.
// ---------------------------------------------------------------------------
__global__ __launch_bounds__(256) void alpha_kernel(const int* __restrict__ mask){
    __shared__ float sT[Ln*Ln];        // [j*64 + i]
    __shared__ float est[Ln*132];      // [j*132 + p], p in [0,128)
    __shared__ float flags[PPB];

    int t  = threadIdx.x;
    int p0 = blockIdx.x * PPB;         // global pair base
    int q0 = p0 + Sn;                  // emit-row base (skip b=0)

    // load exp(T) tile (coalesced, conflict-free)
    {
        const float4* gT4 = (const float4*)gExpT;
        float4* sT4 = (float4*)sT;
        #pragma unroll
        for (int it = 0; it < 4; ++it) sT4[t + it*256] = gT4[t + it*256];
    }
    // load transposed expE tile: 64 rows x 128 pairs
    #pragma unroll
    for (int it = 0; it < 8; ++it){
        int lin = t + it*256;          // 0..2047 float4s
        int j   = lin >> 5;
        int qf  = (lin & 31) << 2;
        float4 v = *(const float4*)(gExpE + (size_t)j*NQ + q0 + qf);
        *(float4*)(est + j*132 + qf) = v;
    }
    if (t < PPB){
        int p = p0 + t;
        int b = 1 + (p >> 9), s = p & 511;
        flags[t] = mask[b*Sn + s] ? 1.0f : 0.0f;
    }
    __syncthreads();

    const int i4 = t & 15;             // i = 4*i4 .. 4*i4+3
    const int pg = t >> 4;             // pairs pg*8 .. pg*8+7
    float acc[4][8];
    #pragma unroll
    for (int k = 0; k < 4; ++k)
        #pragma unroll
        for (int pp = 0; pp < 8; ++pp) acc[k][pp] = 0.0f;

    const float* pT = sT  + (i4 << 2);
    const float* pE = est + (pg << 3);

    #pragma unroll 4
    for (int j = 0; j < 64; ++j){
        float4 tv = *(const float4*)(pT + (j << 6));
        float4 ea = *(const float4*)(pE + j*132);
        float4 eb = *(const float4*)(pE + j*132 + 4);
        float e[8] = {ea.x, ea.y, ea.z, ea.w, eb.x, eb.y, eb.z, eb.w};
        #pragma unroll
        for (int pp = 0; pp < 8; ++pp){
            acc[0][pp] = fmaf(tv.x, e[pp], acc[0][pp]);
            acc[1][pp] = fmaf(tv.y, e[pp], acc[1][pp]);
            acc[2][pp] = fmaf(tv.z, e[pp], acc[2][pp]);
            acc[3][pp] = fmaf(tv.w, e[pp], acc[3][pp]);
        }
    }

    // log + masked accumulate over this thread's 8 pairs (in log2 units)
    float csum[4] = {0.f, 0.f, 0.f, 0.f};
    #pragma unroll
    for (int pp = 0; pp < 8; ++pp){
        float f = flags[(pg << 3) + pp];
        #pragma unroll
        for (int k = 0; k < 4; ++k) csum[k] += f * lg2f_(acc[k][pp]);
    }

    __syncthreads();                   // est no longer needed; alias as reduction buffer
    float* red = est;                  // red[pg*64 + i], 16x64
    #pragma unroll
    for (int k = 0; k < 4; ++k) red[pg*64 + (i4 << 2) + k] = csum[k];
    __syncthreads();

    if (t < Ln){
        float s = 0.f;
        #pragma unroll
        for (int g = 0; g < 16; ++g) s += red[g*64 + t];
        atomicAdd(&g_alpha[t], (double)(s * LN2f));
    }
}

// ---------------------------------------------------------------------------
// Kernel 2: label score.  One block per batch b.
// ---------------------------------------------------------------------------
__global__ __launch_bounds__(256) void score_kernel(
    const float* __restrict__ emit, const int* __restrict__ labels,
    const int* __restrict__ mask, const float* __restrict__ trans,
    const float* __restrict__ strans, const float* __restrict__ etrans)
{
    int b = blockIdx.x, t = threadIdx.x;
    const int* lab = labels + b*Sn;
    const int* mk  = mask + b*Sn;

    float part = 0.f; int cnt = 0;
    for (int s = t; s < Sn; s += 256){
        int m = mk[s] ? 1 : 0;
        cnt += m;
        if (m){
            int l = lab[s];
            float v = emit[((size_t)b*Sn + s)*Ln + l];
            if (s > 0) v += trans[lab[s-1]*Ln + l];
            part += v;
        }
    }
    // reduce
    #pragma unroll
    for (int o = 16; o; o >>= 1){
        part += __shfl_down_sync(0xffffffffu, part, o);
        cnt  += __shfl_down_sync(0xffffffffu, cnt, o);
    }
    __shared__ float sp[8];
    __shared__ int   sc[8];
    int w = t >> 5;
    if ((t & 31) == 0){ sp[w] = part; sc[w] = cnt; }
    __syncthreads();
    if (t == 0){
        double tot = 0.0; int c = 0;
        #pragma unroll
        for (int i = 0; i < 8; ++i){ tot += (double)sp[i]; c += sc[i]; }
        int end = c - 1; if (end < 0) end = 0;
        tot += (double)strans[lab[0]] + (double)etrans[lab[end]];
        atomicAdd(&g_score, tot);
    }
}

// ---------------------------------------------------------------------------
// Kernel 3: finalize.  alpha += emit[0,0,:]; logZ = lse(alpha); out = (logZ-score)/B
// ---------------------------------------------------------------------------
__global__ void fin_kernel(const float* __restrict__ emit, float* __restrict__ out){
    __shared__ double sa[Ln];
    int t = threadIdx.x;
    if (t < Ln) sa[t] = g_alpha[t] + (double)emit[t];   // emit[b=0,s=0,i]
    __syncthreads();
    if (t == 0){
        double m = sa[0];
        for (int i = 1; i < Ln; ++i) if (sa[i] > m) m = sa[i];
        double s = 0.0;
        for (int i = 0; i < Ln; ++i) s += exp(sa[i] - m);
        double logZ = m + log(s);
        out[0] = (float)((logZ - g_score) / (double)Bn);
    }
}

// ---------------------------------------------------------------------------
extern "C" void kernel_launch(void* const* d_in, const int* in_sizes, int n_in,
                              void* d_out, int out_size)
{
    const float* emit   = (const float*)d_in[0];
    const int*   labels = (const int*)d_in[1];
    const int*   mask   = (const int*)d_in[2];
    const float* trans  = (const float*)d_in[3];
    const float* strans = (const float*)d_in[4];
    const float* etrans = (const float*)d_in[5];
    float* out = (float*)d_out;

    init_kernel<<<1, 256>>>(trans);
    transpose_exp_kernel<<<NQ/32, 256>>>(emit);
    alpha_kernel<<<NBLK, 256>>>(mask);
    score_kernel<<<Bn, 256>>>(emit, labels, mask, trans, strans, etrans);
    fin_kernel<<<1, 64>>>(emit, out);
}